// round 16
// baseline (speedup 1.0000x reference)
#include <cuda_runtime.h>
#include <cuda_fp16.h>
#include <math.h>

// Problem constants
#define B_  4
#define L_  1024
#define D_  1024
#define DF_ 4096
#define E_  32768
#define R_  64
#define M_  (B_ * L_)
#define EPS_ 1e-6f

// ---------------------------------------------------------------------------
// Scratch
// ---------------------------------------------------------------------------
__device__ float  g_hsnorm[M_ * D_];
__device__ __half g_hsnorm_h[M_ * D_];
__device__ __half g_q_h[M_ * D_];
__device__ __half g_k_h[M_ * D_];
__device__ __half g_v_h[M_ * D_];
__device__ float  g_t1[M_ * D_];
__device__ __half g_y_h[M_ * D_];
__device__ float  g_out[M_ * D_];
__device__ __half g_out_h[M_ * D_];
__device__ __half g_h1_h[M_ * DF_];
__device__ float  g_f[M_ * D_];
__device__ float  g_score[B_ * E_];
__device__ int    g_perm[B_ * E_];
__device__ int    g_cnt[B_ * L_];
__device__ int    g_off[B_ * (L_ + 1)];
// edge-phase algebra buffers
__device__ float  g_T[M_ * R_];
__device__ __half g_term1_h[M_ * D_];
__device__ __half g_wn_h[M_ * R_];
__device__ float  g_bqr[R_];
// fp16 weights + tables + precomputes
__device__ __half g_wq_h[D_ * D_];
__device__ __half g_wk_h[D_ * D_];
__device__ __half g_wv_h[D_ * D_];
__device__ __half g_wo_h[D_ * D_];
__device__ __half g_w1_h[D_ * DF_];
__device__ __half g_w2_h[DF_ * D_];
__device__ __half g_relpad[128 * D_];   // rows 0..63 = rel fp16, 64..127 = 0
__device__ __half g_rel_t_h[D_ * R_];   // [d][r] = rel[r][d]
__device__ __half g_WqR_h[D_ * R_];     // Wq @ rel^T  [k][r]
__device__ __half g_relWo_h[128 * D_];  // rel @ Wo (rows 0..63 valid)

// ---------------------------------------------------------------------------
// Batched fp32 -> fp16 convert: 7 segments, one launch
// ---------------------------------------------------------------------------
#define NSEG 7
struct CvtArgs {
    const float* src[NSEG];
    __half* dst[NSEG];
    int n[NSEG];
    int cum[NSEG];
};

__global__ void cvt_f2h_multi(CvtArgs a) {
    int blk = blockIdx.x;
    int seg = 0;
    #pragma unroll
    for (int i = 1; i < NSEG; i++) if (blk >= a.cum[i]) seg = i;
    int i = ((blk - a.cum[seg]) * 256 + threadIdx.x) * 8;
    if (i >= a.n[seg]) return;
    const float* x = a.src[seg];
    float4 v0 = *(const float4*)(x + i);
    float4 v1 = *(const float4*)(x + i + 4);
    __half2 h[4];
    h[0] = __floats2half2_rn(v0.x, v0.y);
    h[1] = __floats2half2_rn(v0.z, v0.w);
    h[2] = __floats2half2_rn(v1.x, v1.y);
    h[3] = __floats2half2_rn(v1.z, v1.w);
    *(uint4*)(a.dst[seg] + i) = *(uint4*)h;
}

__global__ void rel_transpose(const float* __restrict__ rel) {
    int idx = blockIdx.x * 256 + threadIdx.x;
    int k = idx >> 6, n = idx & 63;
    g_rel_t_h[idx] = __float2half(rel[n * D_ + k]);
}

// zero rows 64..127 of g_relpad
__global__ void relpad_zero() {
    int i = blockIdx.x * 256 + threadIdx.x;       // 0..65535
    g_relpad[64 * D_ + i] = __float2half(0.f);
}

// bqr[r] = sum_d bq[d] * rel[r][d]
__global__ void bqr_kernel(const float* __restrict__ bq, const float* __restrict__ rel) {
    int r = blockIdx.x, lane = threadIdx.x;
    float acc = 0.f;
    #pragma unroll
    for (int i = 0; i < 32; i++)
        acc = fmaf(bq[lane + 32 * i], rel[r * D_ + lane + 32 * i], acc);
    #pragma unroll
    for (int o = 16; o; o >>= 1) acc += __shfl_xor_sync(0xffffffffu, acc, o);
    if (lane == 0) g_bqr[r] = acc;
}

// ---------------------------------------------------------------------------
// LayerNorm helpers
// ---------------------------------------------------------------------------
__device__ __forceinline__ void row_moments(float4 v, float& mean, float& rstd,
                                            float* sh1, float* sh2) {
    float s  = v.x + v.y + v.z + v.w;
    float sq = v.x * v.x + v.y * v.y + v.z * v.z + v.w * v.w;
    #pragma unroll
    for (int o = 16; o; o >>= 1) {
        s  += __shfl_xor_sync(0xffffffffu, s, o);
        sq += __shfl_xor_sync(0xffffffffu, sq, o);
    }
    int warp = threadIdx.x >> 5, lane = threadIdx.x & 31;
    if (lane == 0) { sh1[warp] = s; sh2[warp] = sq; }
    __syncthreads();
    if (threadIdx.x < 8) {
        s = sh1[threadIdx.x]; sq = sh2[threadIdx.x];
        #pragma unroll
        for (int o = 4; o; o >>= 1) {
            s  += __shfl_xor_sync(0xffu, s, o);
            sq += __shfl_xor_sync(0xffu, sq, o);
        }
        if (threadIdx.x == 0) { sh1[0] = s; sh2[0] = sq; }
    }
    __syncthreads();
    mean = sh1[0] * (1.0f / D_);
    float var = sh2[0] * (1.0f / D_) - mean * mean;
    rstd = rsqrtf(var + EPS_);
}

__global__ void ln_dual_kernel(const float* __restrict__ x, const float* __restrict__ g,
                               const float* __restrict__ b, float* __restrict__ y,
                               __half* y16) {
    __shared__ float sh1[8], sh2[8];
    size_t row = blockIdx.x;
    int t = threadIdx.x;
    float4 v = ((const float4*)(x + row * D_))[t];
    float mean, rstd;
    row_moments(v, mean, rstd, sh1, sh2);
    float4 gv = ((const float4*)g)[t];
    float4 bv = ((const float4*)b)[t];
    float4 o;
    o.x = (v.x - mean) * rstd * gv.x + bv.x;
    o.y = (v.y - mean) * rstd * gv.y + bv.y;
    o.z = (v.z - mean) * rstd * gv.z + bv.z;
    o.w = (v.w - mean) * rstd * gv.w + bv.w;
    ((float4*)(y + row * D_))[t] = o;
    if (y16) {
        __half2 h0 = __floats2half2_rn(o.x, o.y);
        __half2 h1 = __floats2half2_rn(o.z, o.w);
        __half2* p = (__half2*)(y16 + row * D_);
        p[2 * t] = h0; p[2 * t + 1] = h1;
    }
}

// ln over (x + y16half), dual outputs
__global__ void ln_dual2_kernel(const float* __restrict__ x, const __half* __restrict__ xh,
                                const float* __restrict__ g, const float* __restrict__ b,
                                float* __restrict__ y, __half* y16) {
    __shared__ float sh1[8], sh2[8];
    size_t row = blockIdx.x;
    int t = threadIdx.x;
    float4 v = ((const float4*)(x + row * D_))[t];
    uint2 hw = ((const uint2*)(xh + row * D_))[t];
    const __half2* hh = (const __half2*)&hw;
    float2 a0 = __half22float2(hh[0]), a1 = __half22float2(hh[1]);
    v.x += a0.x; v.y += a0.y; v.z += a1.x; v.w += a1.y;
    float mean, rstd;
    row_moments(v, mean, rstd, sh1, sh2);
    float4 gv = ((const float4*)g)[t];
    float4 bv = ((const float4*)b)[t];
    float4 o;
    o.x = (v.x - mean) * rstd * gv.x + bv.x;
    o.y = (v.y - mean) * rstd * gv.y + bv.y;
    o.z = (v.z - mean) * rstd * gv.z + bv.z;
    o.w = (v.w - mean) * rstd * gv.w + bv.w;
    ((float4*)(y + row * D_))[t] = o;
    __half2 h0 = __floats2half2_rn(o.x, o.y);
    __half2 h1 = __floats2half2_rn(o.z, o.w);
    __half2* p = (__half2*)(y16 + row * D_);
    p[2 * t] = h0; p[2 * t + 1] = h1;
}

__global__ void ln_elu_res_kernel(const float* __restrict__ x, const float* __restrict__ g,
                                  const float* __restrict__ b,
                                  const float* __restrict__ hidden,
                                  float* __restrict__ out) {
    __shared__ float sh1[8], sh2[8];
    size_t row = blockIdx.x;
    int t = threadIdx.x;
    float4 v = ((const float4*)(x + row * D_))[t];
    float mean, rstd;
    row_moments(v, mean, rstd, sh1, sh2);
    float4 gv = ((const float4*)g)[t];
    float4 bv = ((const float4*)b)[t];
    float4 hv = ((const float4*)(hidden + row * D_))[t];
    float n0 = (v.x - mean) * rstd * gv.x + bv.x;
    float n1 = (v.y - mean) * rstd * gv.y + bv.y;
    float n2 = (v.z - mean) * rstd * gv.z + bv.z;
    float n3 = (v.w - mean) * rstd * gv.w + bv.w;
    float4 o;
    o.x = hv.x + (n0 > 0.f ? n0 : expm1f(n0));
    o.y = hv.y + (n1 > 0.f ? n1 : expm1f(n1));
    o.z = hv.z + (n2 > 0.f ? n2 : expm1f(n2));
    o.w = hv.w + (n3 > 0.f ? n3 : expm1f(n3));
    ((float4*)(out + row * D_))[t] = o;
}

// ---------------------------------------------------------------------------
// FP16 tensor-core GEMM: CTA 128x128, 8 warps (2x4), warp 64x32, BK=32,
// 4-stage cp.async (wait_group 2), 2 CTAs/SM, ldmatrix A + B.
// ---------------------------------------------------------------------------
__device__ __forceinline__ void mma_f16(float* c, const unsigned* a, const unsigned* b) {
    asm volatile(
        "mma.sync.aligned.m16n8k16.row.col.f32.f16.f16.f32 "
        "{%0,%1,%2,%3}, {%4,%5,%6,%7}, {%8,%9}, {%0,%1,%2,%3};"
        : "+f"(c[0]), "+f"(c[1]), "+f"(c[2]), "+f"(c[3])
        : "r"(a[0]), "r"(a[1]), "r"(a[2]), "r"(a[3]), "r"(b[0]), "r"(b[1]));
}

#define CP16(dst, src) \
    asm volatile("cp.async.cg.shared.global [%0], [%1], 16;\n" :: "r"(dst), "l"(src))

#define APW   20
#define ASTG  (128 * APW)
#define PBHN  136
#define BSTGW (32 * PBHN / 2)
#define NSTAGE 4
#define GEMM_SMEM_BYTES (NSTAGE * (ASTG + BSTGW) * 4)   // 75776

template <bool RELU, bool OUTHALF>
__device__ __forceinline__ void gemm_body_h(
    unsigned* sm, const __half* __restrict__ A, const __half* __restrict__ Bm,
    const float* bias, const float* res, float* C32, __half* C16,
    int N, int K, int bm, int bn) {
    unsigned* As = sm;
    unsigned* Bs = sm + NSTAGE * ASTG;
    int tid = threadIdx.x;
    int warp = tid >> 5, lane = tid & 31;
    int g = lane >> 2, tg = lane & 3;
    int wm = (warp & 1) * 64, wn = (warp >> 1) * 32;

    int arow = tid >> 1;
    const __half* aptr = A + (size_t)(bm + arow) * K + (tid & 1) * 16;
    unsigned a_dst = (unsigned)__cvta_generic_to_shared(As + arow * APW + (tid & 1) * 8);
    int brow = tid >> 3, bc = (tid & 7) * 16;
    const __half* bptr = Bm + (size_t)brow * N + bn + bc;
    unsigned b_dst = (unsigned)__cvta_generic_to_shared((__half*)Bs + brow * PBHN + bc);

    int quad = lane >> 3, j = lane & 7;
    int lrow = (quad & 1) * 8 + j;
    int lcol = wn + (quad >> 1) * 8;
    unsigned b_frag_base = (unsigned)__cvta_generic_to_shared((__half*)Bs + lrow * PBHN + lcol);
    unsigned a_frag_base = (unsigned)__cvta_generic_to_shared(
        (__half*)As + lrow * (APW * 2) + (quad >> 1) * 8);

    int ntiles = K >> 5;

    #pragma unroll
    for (int s = 0; s < NSTAGE - 1; s++) {
        if (s < ntiles) {
            const __half* ap = aptr + s * 32;
            const __half* bp = bptr + (size_t)s * 32 * N;
            unsigned ad = a_dst + s * ASTG * 4;
            unsigned bd = b_dst + s * BSTGW * 4;
            CP16(ad, ap); CP16(ad + 16, ap + 8);
            CP16(bd, bp); CP16(bd + 16, bp + 8);
        }
        asm volatile("cp.async.commit_group;\n");
    }

    float acc[4][4][4];
    #pragma unroll
    for (int mt = 0; mt < 4; mt++)
        #pragma unroll
        for (int nt = 0; nt < 4; nt++)
            #pragma unroll
            for (int r = 0; r < 4; r++) acc[mt][nt][r] = 0.f;

    for (int kt = 0; kt < ntiles; kt++) {
        asm volatile("cp.async.wait_group %0;\n" :: "n"(NSTAGE - 2));
        __syncthreads();

        int nx = kt + NSTAGE - 1;
        if (nx < ntiles) {
            int st = nx % NSTAGE;
            const __half* ap = aptr + nx * 32;
            const __half* bp = bptr + (size_t)nx * 32 * N;
            unsigned ad = a_dst + st * ASTG * 4;
            unsigned bd = b_dst + st * BSTGW * 4;
            CP16(ad, ap); CP16(ad + 16, ap + 8);
            CP16(bd, bp); CP16(bd + 16, bp + 8);
        }
        asm volatile("cp.async.commit_group;\n");

        int cur = kt % NSTAGE;
        unsigned asm_base = a_frag_base + cur * ASTG * 4 + wm * APW * 4;
        unsigned bsm = b_frag_base + cur * BSTGW * 4;
        #pragma unroll
        for (int ks = 0; ks < 2; ks++) {
            unsigned af[4][4];
            #pragma unroll
            for (int mt = 0; mt < 4; mt++) {
                unsigned aaddr = asm_base + mt * 16 * APW * 4 + ks * 32;
                asm volatile(
                    "ldmatrix.sync.aligned.m8n8.x4.shared.b16 {%0,%1,%2,%3}, [%4];"
                    : "=r"(af[mt][0]), "=r"(af[mt][1]), "=r"(af[mt][2]), "=r"(af[mt][3])
                    : "r"(aaddr));
            }
            unsigned bf[4][2];
            #pragma unroll
            for (int nb = 0; nb < 2; nb++) {
                unsigned addr = bsm + ks * 16 * (PBHN * 2) + nb * 32;
                asm volatile(
                    "ldmatrix.sync.aligned.m8n8.x4.trans.shared.b16 {%0,%1,%2,%3}, [%4];"
                    : "=r"(bf[2 * nb][0]), "=r"(bf[2 * nb][1]),
                      "=r"(bf[2 * nb + 1][0]), "=r"(bf[2 * nb + 1][1])
                    : "r"(addr));
            }
            #pragma unroll
            for (int mt = 0; mt < 4; mt++)
                #pragma unroll
                for (int nt = 0; nt < 4; nt++)
                    mma_f16(acc[mt][nt], af[mt], bf[nt]);
        }
    }

    #pragma unroll
    for (int mt = 0; mt < 4; mt++) {
        #pragma unroll
        for (int nt = 0; nt < 4; nt++) {
            int col = bn + wn + nt * 8 + tg * 2;
            #pragma unroll
            for (int h = 0; h < 2; h++) {
                int row = bm + wm + mt * 16 + g + h * 8;
                float vx = acc[mt][nt][2 * h];
                float vy = acc[mt][nt][2 * h + 1];
                if (bias) {
                    float2 bb = *(const float2*)(bias + col);
                    vx += bb.x; vy += bb.y;
                }
                if (res) {
                    float2 rr = *(const float2*)(res + (size_t)row * N + col);
                    vx += rr.x; vy += rr.y;
                }
                if (RELU) { vx = fmaxf(vx, 0.f); vy = fmaxf(vy, 0.f); }
                if (OUTHALF)
                    *(__half2*)(C16 + (size_t)row * N + col) = __floats2half2_rn(vx, vy);
                else
                    *(float2*)(C32 + (size_t)row * N + col) = make_float2(vx, vy);
            }
        }
    }
}

template <bool RELU, bool OUTHALF>
__global__ __launch_bounds__(256, 2) void mma_gemm_h(
    const __half* __restrict__ A, const __half* __restrict__ Bm,
    const float* bias, const float* res, float* C32, __half* C16,
    int M, int N, int K) {
    extern __shared__ unsigned sm[];
    gemm_body_h<RELU, OUTHALF>(sm, A, Bm, bias, res, C32, C16, N, K,
                               blockIdx.y * 128, blockIdx.x * 128);
}

struct QKVArgs {
    const __half* Bm[3];
    const float* bias[3];
    __half* C[3];
};

__global__ __launch_bounds__(256, 2) void mma_gemm_qkv(
    const __half* __restrict__ A, QKVArgs args, int M, int N, int K) {
    extern __shared__ unsigned sm[];
    int z = blockIdx.z;
    gemm_body_h<false, true>(sm, A, args.Bm[z], args.bias[z], nullptr, nullptr,
                             args.C[z], N, K, blockIdx.y * 128, blockIdx.x * 128);
}

// ---------------------------------------------------------------------------
// Small-N GEMM: C[M,64] = A[M,K] @ B[K,64]; fp32 or fp16 out
// ---------------------------------------------------------------------------
#define TAPW   20
#define TASTG  (128 * TAPW)
#define TNST   3
#define PB64   72
#define BSTG64 (32 * PB64 / 2)

template <bool OUTH>
__global__ __launch_bounds__(256, 2) void gemm_T64(
    const __half* __restrict__ A, const __half* __restrict__ Bm,
    float* C32, __half* C16, int K) {
    __shared__ unsigned smT[TNST * (TASTG + BSTG64)];
    unsigned* As = smT;
    unsigned* Bs = smT + TNST * TASTG;
    const int N = R_;
    int tid = threadIdx.x;
    int warp = tid >> 5, lane = tid & 31;
    int g = lane >> 2, tg = lane & 3;
    int wm = (warp & 3) * 32, wn = (warp >> 2) * 32;
    int bm = blockIdx.y * 128;

    int arow = tid >> 1;
    const __half* aptr = A + (size_t)(bm + arow) * K + (tid & 1) * 16;
    unsigned a_dst = (unsigned)__cvta_generic_to_shared(As + arow * TAPW + (tid & 1) * 8);
    int brow = tid >> 3, bc = (tid & 7) * 8;
    const __half* bptr = Bm + (size_t)brow * N + bc;
    unsigned b_dst = (unsigned)__cvta_generic_to_shared((__half*)Bs + brow * PB64 + bc);

    int quad = lane >> 3, j = lane & 7;
    int lrow = (quad & 1) * 8 + j;
    int lcol = wn + (quad >> 1) * 8;
    unsigned b_frag_base = (unsigned)__cvta_generic_to_shared((__half*)Bs + lrow * PB64 + lcol);

    int ntiles = K >> 5;
    #pragma unroll
    for (int s = 0; s < TNST - 1; s++) {
        unsigned ad = a_dst + s * TASTG * 4;
        unsigned bd = b_dst + s * BSTG64 * 4;
        CP16(ad, aptr + s * 32); CP16(ad + 16, aptr + s * 32 + 8);
        CP16(bd, bptr + (size_t)s * 32 * N);
        asm volatile("cp.async.commit_group;\n");
    }

    float acc[2][4][4];
    #pragma unroll
    for (int mt = 0; mt < 2; mt++)
        #pragma unroll
        for (int nt = 0; nt < 4; nt++)
            #pragma unroll
            for (int r = 0; r < 4; r++) acc[mt][nt][r] = 0.f;

    for (int kt = 0; kt < ntiles; kt++) {
        asm volatile("cp.async.wait_group %0;\n" :: "n"(TNST - 2));
        __syncthreads();
        int nx = kt + TNST - 1;
        if (nx < ntiles) {
            int st = nx % TNST;
            unsigned ad = a_dst + st * TASTG * 4;
            unsigned bd = b_dst + st * BSTG64 * 4;
            CP16(ad, aptr + nx * 32); CP16(ad + 16, aptr + nx * 32 + 8);
            CP16(bd, bptr + (size_t)nx * 32 * N);
        }
        asm volatile("cp.async.commit_group;\n");

        int cur = kt % TNST;
        const unsigned* Ab = As + cur * TASTG;
        unsigned bsm = b_frag_base + cur * BSTG64 * 4;
        #pragma unroll
        for (int ks = 0; ks < 2; ks++) {
            unsigned af[2][4];
            #pragma unroll
            for (int mt = 0; mt < 2; mt++) {
                const unsigned* p = Ab + (wm + mt * 16 + g) * TAPW + ks * 8 + tg;
                af[mt][0] = p[0];
                af[mt][1] = p[8 * TAPW];
                af[mt][2] = p[4];
                af[mt][3] = p[8 * TAPW + 4];
            }
            unsigned bf[4][2];
            #pragma unroll
            for (int nb = 0; nb < 2; nb++) {
                unsigned addr = bsm + ks * 16 * (PB64 * 2) + nb * 32;
                asm volatile(
                    "ldmatrix.sync.aligned.m8n8.x4.trans.shared.b16 {%0,%1,%2,%3}, [%4];"
                    : "=r"(bf[2 * nb][0]), "=r"(bf[2 * nb][1]),
                      "=r"(bf[2 * nb + 1][0]), "=r"(bf[2 * nb + 1][1])
                    : "r"(addr));
            }
            #pragma unroll
            for (int mt = 0; mt < 2; mt++)
                #pragma unroll
                for (int nt = 0; nt < 4; nt++)
                    mma_f16(acc[mt][nt], af[mt], bf[nt]);
        }
    }

    #pragma unroll
    for (int mt = 0; mt < 2; mt++)
        #pragma unroll
        for (int nt = 0; nt < 4; nt++) {
            int col = wn + nt * 8 + tg * 2;
            #pragma unroll
            for (int h = 0; h < 2; h++) {
                int row = bm + wm + mt * 16 + g + h * 8;
                if (OUTH)
                    *(__half2*)(C16 + (size_t)row * N + col) =
                        __floats2half2_rn(acc[mt][nt][2 * h], acc[mt][nt][2 * h + 1]);
                else
                    *(float2*)(C32 + (size_t)row * N + col) =
                        make_float2(acc[mt][nt][2 * h], acc[mt][nt][2 * h + 1]);
            }
        }
}

// ---------------------------------------------------------------------------
// Edge scores: k[src].q[dst] + T[dst,rel] + bqr[rel]
// ---------------------------------------------------------------------------
__global__ void score_kernel(const __half* __restrict__ Q, const __half* __restrict__ Km,
                             const float* __restrict__ T,
                             const int* __restrict__ src, const int* __restrict__ dst,
                             const int* __restrict__ rel, float* __restrict__ score) {
    int idx = blockIdx.x * 4 + threadIdx.y;
    int b = idx >> 15;
    int lane = threadIdx.x;
    int s = src[idx], d = dst[idx], r = rel[idx];
    const __half* kr = Km + ((size_t)b * L_ + s) * D_;
    const __half* qr = Q + ((size_t)b * L_ + d) * D_;
    float acc = 0.f;
    #pragma unroll
    for (int i = 0; i < 4; i++) {
        int c = (lane + 32 * i) * 8;
        uint4 kv = *(const uint4*)(kr + c);
        uint4 qv = *(const uint4*)(qr + c);
        const __half2* kh = (const __half2*)&kv;
        const __half2* qh = (const __half2*)&qv;
        #pragma unroll
        for (int j = 0; j < 4; j++) {
            __half2 p = __hmul2(kh[j], qh[j]);
            float2 pf = __half22float2(p);
            acc += pf.x + pf.y;
        }
    }
    #pragma unroll
    for (int o = 16; o; o >>= 1) acc += __shfl_xor_sync(0xffffffffu, acc, o);
    if (lane == 0) {
        float sc = (acc + T[((size_t)b * L_ + d) * R_ + r] + g_bqr[r]) * 0.03125f;
        sc = fminf(fmaxf(sc, -10.f), 10.f);
        score[idx] = expf(sc);
    }
}

// ---------------------------------------------------------------------------
// Deterministic binning
// ---------------------------------------------------------------------------
__global__ void zero_cnt_kernel() {
    int i = blockIdx.x * 256 + threadIdx.x;
    if (i < B_ * L_) g_cnt[i] = 0;
}

__global__ void hist_kernel(const int* __restrict__ edge_dst) {
    int idx = blockIdx.x * 256 + threadIdx.x;
    if (idx < B_ * E_) atomicAdd(&g_cnt[(idx >> 15) * L_ + edge_dst[idx]], 1);
}

__global__ void scan_kernel() {
    int b = blockIdx.x, t = threadIdx.x;
    __shared__ int s[L_];
    int c = g_cnt[b * L_ + t];
    s[t] = c;
    __syncthreads();
    for (int off = 1; off < L_; off <<= 1) {
        int v = (t >= off) ? s[t - off] : 0;
        __syncthreads();
        s[t] += v;
        __syncthreads();
    }
    g_off[b * (L_ + 1) + t] = s[t] - c;
    if (t == L_ - 1) g_off[b * (L_ + 1) + L_] = s[t];
}

__global__ void fill_block_kernel(const int* __restrict__ edge_dst) {
    __shared__ int sd[1024];
    int b = blockIdx.x >> 7;
    int nodebase = (blockIdx.x & 127) * 8;
    int warp = threadIdx.x >> 5, lane = threadIdx.x & 31;
    int node = nodebase + warp;
    int w = g_off[b * (L_ + 1) + node];
    int* pb = g_perm + b * E_;
    const int* dv = edge_dst + b * E_;
    for (int base = 0; base < E_; base += 1024) {
        __syncthreads();
        #pragma unroll
        for (int i = 0; i < 4; i++) sd[threadIdx.x + 256 * i] = dv[base + threadIdx.x + 256 * i];
        __syncthreads();
        for (int c = 0; c < 1024; c += 32) {
            int d = sd[c + lane];
            unsigned m = __ballot_sync(0xffffffffu, d == node);
            if (d == node) pb[w + __popc(m & ((1u << lane) - 1))] = base + c + lane;
            w += __popc(m);
        }
    }
}

// ---------------------------------------------------------------------------
// Fused aggregation (smem-staged): term1_h = (sum s*v)/z (fp16),
// Wn[r] = (sum_{rel=r} s)/z
// ---------------------------------------------------------------------------
__global__ void agg_fused_kernel(const __half* __restrict__ V,
                                 const int* __restrict__ src,
                                 const int* __restrict__ rel,
                                 const float* __restrict__ score) {
    __shared__ float ss[256];
    __shared__ int   ssn[256];
    __shared__ int   srl[256];
    int node = blockIdx.x, b = blockIdx.y;
    int t = threadIdx.x;
    int beg = g_off[b * (L_ + 1) + node];
    int end = g_off[b * (L_ + 1) + node + 1];
    int deg = end - beg;
    const int* pb = g_perm + b * E_;
    float4 acc = make_float4(0.f, 0.f, 0.f, 0.f);
    float z = 0.f;
    float W = 0.f;

    for (int base = 0; base < deg; base += 256) {
        int n = deg - base;
        if (n > 256) n = 256;
        if (t < n) {
            int e = pb[beg + base + t];
            ss[t]  = score[b * E_ + e];
            ssn[t] = src[b * E_ + e];
            srl[t] = rel[b * E_ + e];
        }
        __syncthreads();
        for (int i = 0; i < n; i++) {
            float s = ss[i];
            int sn = ssn[i];
            uint2 vw = *(const uint2*)(V + ((size_t)b * L_ + sn) * D_ + 4 * t);
            const __half2* vh = (const __half2*)&vw;
            float2 v0 = __half22float2(vh[0]), v1 = __half22float2(vh[1]);
            acc.x = fmaf(s, v0.x, acc.x);
            acc.y = fmaf(s, v0.y, acc.y);
            acc.z = fmaf(s, v1.x, acc.z);
            acc.w = fmaf(s, v1.y, acc.w);
            z += s;
        }
        if (t < R_) {
            for (int i = 0; i < n; i++)
                if (srl[i] == t) W += ss[i];
        }
        __syncthreads();
    }

    float inv = 1.0f / z;
    __half2* dst = (__half2*)(g_term1_h + ((size_t)b * L_ + node) * D_ + 4 * t);
    dst[0] = __floats2half2_rn(acc.x * inv, acc.y * inv);
    dst[1] = __floats2half2_rn(acc.z * inv, acc.w * inv);
    if (t < R_)
        g_wn_h[((size_t)b * L_ + node) * R_ + t] = __float2half(W * inv);
}

// ---------------------------------------------------------------------------
// Launch — DAG with three side streams (conversions/precomputes, binning,
// T-GEMM + Y-GEMM).
// ---------------------------------------------------------------------------
extern "C" void kernel_launch(void* const* d_in, const int* in_sizes, int n_in,
                              void* d_out, int out_size) {
    const float* hidden  = (const float*)d_in[0];
    const float* rel_tab = (const float*)d_in[1];
    const float* Wq = (const float*)d_in[2];
    const float* bq = (const float*)d_in[3];
    const float* Wk = (const float*)d_in[4];
    const float* Wv = (const float*)d_in[5];
    const float* Wo = (const float*)d_in[6];
    const float* bo = (const float*)d_in[7];
    const float* ln0g = (const float*)d_in[8];
    const float* ln0b = (const float*)d_in[9];
    const float* ln1g = (const float*)d_in[10];
    const float* ln1b = (const float*)d_in[11];
    const float* W1 = (const float*)d_in[12];
    const float* b1 = (const float*)d_in[13];
    const float* W2 = (const float*)d_in[14];
    const float* b2 = (const float*)d_in[15];
    const float* ln2g = (const float*)d_in[16];
    const float* ln2b = (const float*)d_in[17];
    const int* esrc = (const int*)d_in[18];
    const int* edst = (const int*)d_in[19];
    const int* erel = (const int*)d_in[20];
    float* out = (float*)d_out;

    float *p_hsnorm, *p_t1, *p_out, *p_f, *p_score, *p_T;
    __half *p_hsnorm_h, *p_q_h, *p_k_h, *p_v_h, *p_out_h, *p_h1_h, *p_wn_h;
    __half *p_term1_h, *p_y_h, *p_relpad, *p_WqR_h, *p_relWo_h;
    __half *p_wq_h, *p_wk_h, *p_wv_h, *p_wo_h, *p_w1_h, *p_w2_h, *p_rel_t_h;
    cudaGetSymbolAddress((void**)&p_hsnorm, g_hsnorm);
    cudaGetSymbolAddress((void**)&p_hsnorm_h, g_hsnorm_h);
    cudaGetSymbolAddress((void**)&p_q_h, g_q_h);
    cudaGetSymbolAddress((void**)&p_k_h, g_k_h);
    cudaGetSymbolAddress((void**)&p_v_h, g_v_h);
    cudaGetSymbolAddress((void**)&p_t1, g_t1);
    cudaGetSymbolAddress((void**)&p_y_h, g_y_h);
    cudaGetSymbolAddress((void**)&p_out, g_out);
    cudaGetSymbolAddress((void**)&p_out_h, g_out_h);
    cudaGetSymbolAddress((void**)&p_h1_h, g_h1_h);
    cudaGetSymbolAddress((void**)&p_f, g_f);
    cudaGetSymbolAddress((void**)&p_score, g_score);
    cudaGetSymbolAddress((void**)&p_T, g_T);
    cudaGetSymbolAddress((void**)&p_term1_h, g_term1_h);
    cudaGetSymbolAddress((void**)&p_wn_h, g_wn_h);
    cudaGetSymbolAddress((void**)&p_relpad, g_relpad);
    cudaGetSymbolAddress((void**)&p_WqR_h, g_WqR_h);
    cudaGetSymbolAddress((void**)&p_relWo_h, g_relWo_h);
    cudaGetSymbolAddress((void**)&p_wq_h, g_wq_h);
    cudaGetSymbolAddress((void**)&p_wk_h, g_wk_h);
    cudaGetSymbolAddress((void**)&p_wv_h, g_wv_h);
    cudaGetSymbolAddress((void**)&p_wo_h, g_wo_h);
    cudaGetSymbolAddress((void**)&p_w1_h, g_w1_h);
    cudaGetSymbolAddress((void**)&p_w2_h, g_w2_h);
    cudaGetSymbolAddress((void**)&p_rel_t_h, g_rel_t_h);

    cudaFuncSetAttribute((const void*)mma_gemm_h<false, false>,
                         cudaFuncAttributeMaxDynamicSharedMemorySize, GEMM_SMEM_BYTES);
    cudaFuncSetAttribute((const void*)mma_gemm_h<false, true>,
                         cudaFuncAttributeMaxDynamicSharedMemorySize, GEMM_SMEM_BYTES);
    cudaFuncSetAttribute((const void*)mma_gemm_h<true, true>,
                         cudaFuncAttributeMaxDynamicSharedMemorySize, GEMM_SMEM_BYTES);
    cudaFuncSetAttribute((const void*)mma_gemm_qkv,
                         cudaFuncAttributeMaxDynamicSharedMemorySize, GEMM_SMEM_BYTES);

    cudaStream_t sA, sB, sC;
    cudaStreamCreateWithFlags(&sA, cudaStreamNonBlocking);
    cudaStreamCreateWithFlags(&sB, cudaStreamNonBlocking);
    cudaStreamCreateWithFlags(&sC, cudaStreamNonBlocking);
    cudaEvent_t evFork, evA, evA2, evRW, evB, evLn0, evT, evAgg, evY;
    cudaEventCreateWithFlags(&evFork, cudaEventDisableTiming);
    cudaEventCreateWithFlags(&evA, cudaEventDisableTiming);
    cudaEventCreateWithFlags(&evA2, cudaEventDisableTiming);
    cudaEventCreateWithFlags(&evRW, cudaEventDisableTiming);
    cudaEventCreateWithFlags(&evB, cudaEventDisableTiming);
    cudaEventCreateWithFlags(&evLn0, cudaEventDisableTiming);
    cudaEventCreateWithFlags(&evT, cudaEventDisableTiming);
    cudaEventCreateWithFlags(&evAgg, cudaEventDisableTiming);
    cudaEventCreateWithFlags(&evY, cudaEventDisableTiming);

    cudaEventRecord(evFork, 0);
    cudaStreamWaitEvent(sA, evFork, 0);
    cudaStreamWaitEvent(sB, evFork, 0);
    cudaStreamWaitEvent(sC, evFork, 0);

    // Branch A: conversions, then weight-only precomputes
    {
        CvtArgs a;
        const float* srcs[NSEG] = {Wq, Wk, Wv, Wo, W1, W2, rel_tab};
        __half* dsts[NSEG] = {p_wq_h, p_wk_h, p_wv_h, p_wo_h, p_w1_h, p_w2_h, p_relpad};
        int ns[NSEG] = {D_ * D_, D_ * D_, D_ * D_, D_ * D_, D_ * DF_, DF_ * D_, R_ * D_};
        int cum = 0;
        for (int i = 0; i < NSEG; i++) {
            a.src[i] = srcs[i]; a.dst[i] = dsts[i]; a.n[i] = ns[i];
            a.cum[i] = cum;
            cum += (ns[i] + 2047) / 2048;
        }
        cvt_f2h_multi<<<cum, 256, 0, sA>>>(a);
    }
    rel_transpose<<<(D_ * R_) / 256, 256, 0, sA>>>(rel_tab);
    relpad_zero<<<(64 * D_) / 256, 256, 0, sA>>>();
    cudaEventRecord(evA, sA);    // weights fp16 ready for QKV
    // WqR = Wq @ rel_t  [1024, 64] fp16 ; bqr = bq . rel
    gemm_T64<true><<<dim3(1, D_ / 128), 256, 0, sA>>>(p_wq_h, p_rel_t_h, nullptr, p_WqR_h, D_);
    bqr_kernel<<<R_, 32, 0, sA>>>(bq, rel_tab);
    cudaEventRecord(evA2, sA);
    // relWo = relpad @ Wo  [128, 1024] fp16
    mma_gemm_h<false, true><<<dim3(D_ / 128, 1), 256, GEMM_SMEM_BYTES, sA>>>(
        p_relpad, p_wo_h, nullptr, nullptr, nullptr, p_relWo_h, 128, D_, D_);
    cudaEventRecord(evRW, sA);

    // Branch B: edge binning
    zero_cnt_kernel<<<(B_ * L_) / 256, 256, 0, sB>>>();
    hist_kernel<<<(B_ * E_) / 256, 256, 0, sB>>>(edst);
    scan_kernel<<<B_, L_, 0, sB>>>();
    fill_block_kernel<<<512, 256, 0, sB>>>(edst);
    cudaEventRecord(evB, sB);

    // Main: ln0
    ln_dual_kernel<<<M_, 256>>>(hidden, ln0g, ln0b, p_hsnorm, p_hsnorm_h);
    cudaEventRecord(evLn0, 0);

    cudaStreamWaitEvent(0, evA, 0);

    // QKV (main) ; T = hsnorm @ WqR (stream C, concurrent)
    QKVArgs qkv;
    qkv.Bm[0] = p_wq_h; qkv.Bm[1] = p_wk_h; qkv.Bm[2] = p_wv_h;
    qkv.bias[0] = bq; qkv.bias[1] = nullptr; qkv.bias[2] = nullptr;
    qkv.C[0] = p_q_h; qkv.C[1] = p_k_h; qkv.C[2] = p_v_h;
    dim3 gQKV(D_ / 128, M_ / 128, 3);
    mma_gemm_qkv<<<gQKV, 256, GEMM_SMEM_BYTES>>>(p_hsnorm_h, qkv, M_, D_, D_);

    cudaStreamWaitEvent(sC, evLn0, 0);
    cudaStreamWaitEvent(sC, evA2, 0);
    gemm_T64<false><<<dim3(1, M_ / 128), 256, 0, sC>>>(p_hsnorm_h, p_WqR_h, p_T, nullptr, D_);
    cudaEventRecord(evT, sC);

    // score after QKV + T
    cudaStreamWaitEvent(0, evT, 0);
    score_kernel<<<(B_ * E_) / 4, dim3(32, 4)>>>(p_q_h, p_k_h, p_T, esrc, edst, erel, p_score);

    cudaStreamWaitEvent(0, evB, 0);
    agg_fused_kernel<<<dim3(L_, B_), 256>>>(p_v_h, esrc, erel, p_score);
    cudaEventRecord(evAgg, 0);

    // X = term1 @ Wo + bo + hsnorm (main) ; Y = Wn @ relWo (stream C)
    dim3 gD(D_ / 128, M_ / 128);
    mma_gemm_h<false, false><<<gD, 256, GEMM_SMEM_BYTES>>>(
        p_term1_h, p_wo_h, bo, p_hsnorm, p_t1, nullptr, M_, D_, D_);

    cudaStreamWaitEvent(sC, evAgg, 0);
    cudaStreamWaitEvent(sC, evRW, 0);
    mma_gemm_h<false, true><<<gD, 256, GEMM_SMEM_BYTES, sC>>>(
        p_wn_h, p_relWo_h, nullptr, nullptr, nullptr, p_y_h, M_, D_, R_);
    cudaEventRecord(evY, sC);

    cudaStreamWaitEvent(0, evY, 0);
    ln_dual2_kernel<<<M_, 256>>>(p_t1, p_y_h, ln1g, ln1b, p_out, p_out_h);

    // FFN
    dim3 gDF(DF_ / 128, M_ / 128);
    mma_gemm_h<true, true><<<gDF, 256, GEMM_SMEM_BYTES>>>(
        p_out_h, p_w1_h, b1, nullptr, nullptr, p_h1_h, M_, DF_, D_);
    mma_gemm_h<false, false><<<gD, 256, GEMM_SMEM_BYTES>>>(
        p_h1_h, p_w2_h, b2, p_out, p_f, nullptr, M_, D_, DF_);

    // final
    ln_elu_res_kernel<<<M_, 256>>>(p_f, ln2g, ln2b, hidden, out);

    cudaEventDestroy(evFork); cudaEventDestroy(evA); cudaEventDestroy(evA2);
    cudaEventDestroy(evRW); cudaEventDestroy(evB); cudaEventDestroy(evLn0);
    cudaEventDestroy(evT); cudaEventDestroy(evAgg); cudaEventDestroy(evY);
    cudaStreamDestroy(sA); cudaStreamDestroy(sB); cudaStreamDestroy(sC);
}

// round 17
// speedup vs baseline: 1.0322x; 1.0322x over previous
#include <cuda_runtime.h>
#include <cuda_fp16.h>
#include <math.h>

// Problem constants
#define B_  4
#define L_  1024
#define D_  1024
#define DF_ 4096
#define E_  32768
#define R_  64
#define M_  (B_ * L_)
#define EPS_ 1e-6f

// ---------------------------------------------------------------------------
// Scratch
// ---------------------------------------------------------------------------
__device__ float  g_hsnorm[M_ * D_];
__device__ __half g_hsnorm_h[M_ * D_];
__device__ __half g_q_h[M_ * D_];
__device__ __half g_k_h[M_ * D_];
__device__ __half g_v_h[M_ * D_];
__device__ __half g_o_h[M_ * D_];
__device__ float  g_t1[M_ * D_];
__device__ float  g_out[M_ * D_];
__device__ __half g_out_h[M_ * D_];
__device__ __half g_h1_h[M_ * DF_];
__device__ float  g_f[M_ * D_];
__device__ float  g_score[B_ * E_];
__device__ int    g_perm[B_ * E_];
__device__ int    g_cnt[B_ * L_];
__device__ int    g_off[B_ * (L_ + 1)];
// edge-phase algebra buffers
__device__ float  g_T[M_ * R_];
__device__ float  g_term1[M_ * D_];
__device__ __half g_wn_h[M_ * R_];
__device__ float  g_bqr[R_];
// fp16 weights + tables + precomputes
__device__ __half g_wq_h[D_ * D_];
__device__ __half g_wk_h[D_ * D_];
__device__ __half g_wv_h[D_ * D_];
__device__ __half g_wo_h[D_ * D_];
__device__ __half g_w1_h[D_ * DF_];
__device__ __half g_w2_h[DF_ * D_];
__device__ __half g_rel_h[R_ * D_];    // [r][d] row-major: B for o-GEMM (K=64)
__device__ __half g_rel_t_h[D_ * R_];  // [d][r]: B for WqR/T GEMM
__device__ __half g_WqR_h[D_ * R_];    // Wq @ rel^T  [k][r]

// ---------------------------------------------------------------------------
// Batched fp32 -> fp16 convert: 7 segments, one launch
// ---------------------------------------------------------------------------
#define NSEG 7
struct CvtArgs {
    const float* src[NSEG];
    __half* dst[NSEG];
    int n[NSEG];
    int cum[NSEG];
};

__global__ void cvt_f2h_multi(CvtArgs a) {
    int blk = blockIdx.x;
    int seg = 0;
    #pragma unroll
    for (int i = 1; i < NSEG; i++) if (blk >= a.cum[i]) seg = i;
    int i = ((blk - a.cum[seg]) * 256 + threadIdx.x) * 8;
    if (i >= a.n[seg]) return;
    const float* x = a.src[seg];
    float4 v0 = *(const float4*)(x + i);
    float4 v1 = *(const float4*)(x + i + 4);
    __half2 h[4];
    h[0] = __floats2half2_rn(v0.x, v0.y);
    h[1] = __floats2half2_rn(v0.z, v0.w);
    h[2] = __floats2half2_rn(v1.x, v1.y);
    h[3] = __floats2half2_rn(v1.z, v1.w);
    *(uint4*)(a.dst[seg] + i) = *(uint4*)h;
}

__global__ void rel_transpose(const float* __restrict__ rel) {
    int idx = blockIdx.x * 256 + threadIdx.x;
    int k = idx >> 6, n = idx & 63;
    g_rel_t_h[idx] = __float2half(rel[n * D_ + k]);
}

// bqr[r] = sum_d bq[d] * rel[r][d]
__global__ void bqr_kernel(const float* __restrict__ bq, const float* __restrict__ rel) {
    int r = blockIdx.x, lane = threadIdx.x;
    float acc = 0.f;
    #pragma unroll
    for (int i = 0; i < 32; i++)
        acc = fmaf(bq[lane + 32 * i], rel[r * D_ + lane + 32 * i], acc);
    #pragma unroll
    for (int o = 16; o; o >>= 1) acc += __shfl_xor_sync(0xffffffffu, acc, o);
    if (lane == 0) g_bqr[r] = acc;
}

// ---------------------------------------------------------------------------
// LayerNorm helpers
// ---------------------------------------------------------------------------
__device__ __forceinline__ void row_moments(float4 v, float& mean, float& rstd,
                                            float* sh1, float* sh2) {
    float s  = v.x + v.y + v.z + v.w;
    float sq = v.x * v.x + v.y * v.y + v.z * v.z + v.w * v.w;
    #pragma unroll
    for (int o = 16; o; o >>= 1) {
        s  += __shfl_xor_sync(0xffffffffu, s, o);
        sq += __shfl_xor_sync(0xffffffffu, sq, o);
    }
    int warp = threadIdx.x >> 5, lane = threadIdx.x & 31;
    if (lane == 0) { sh1[warp] = s; sh2[warp] = sq; }
    __syncthreads();
    if (threadIdx.x < 8) {
        s = sh1[threadIdx.x]; sq = sh2[threadIdx.x];
        #pragma unroll
        for (int o = 4; o; o >>= 1) {
            s  += __shfl_xor_sync(0xffu, s, o);
            sq += __shfl_xor_sync(0xffu, sq, o);
        }
        if (threadIdx.x == 0) { sh1[0] = s; sh2[0] = sq; }
    }
    __syncthreads();
    mean = sh1[0] * (1.0f / D_);
    float var = sh2[0] * (1.0f / D_) - mean * mean;
    rstd = rsqrtf(var + EPS_);
}

__global__ void ln_dual_kernel(const float* __restrict__ x, const float* __restrict__ g,
                               const float* __restrict__ b, float* __restrict__ y,
                               __half* y16) {
    __shared__ float sh1[8], sh2[8];
    size_t row = blockIdx.x;
    int t = threadIdx.x;
    float4 v = ((const float4*)(x + row * D_))[t];
    float mean, rstd;
    row_moments(v, mean, rstd, sh1, sh2);
    float4 gv = ((const float4*)g)[t];
    float4 bv = ((const float4*)b)[t];
    float4 o;
    o.x = (v.x - mean) * rstd * gv.x + bv.x;
    o.y = (v.y - mean) * rstd * gv.y + bv.y;
    o.z = (v.z - mean) * rstd * gv.z + bv.z;
    o.w = (v.w - mean) * rstd * gv.w + bv.w;
    ((float4*)(y + row * D_))[t] = o;
    if (y16) {
        __half2 h0 = __floats2half2_rn(o.x, o.y);
        __half2 h1 = __floats2half2_rn(o.z, o.w);
        __half2* p = (__half2*)(y16 + row * D_);
        p[2 * t] = h0; p[2 * t + 1] = h1;
    }
}

__global__ void ln_elu_res_kernel(const float* __restrict__ x, const float* __restrict__ g,
                                  const float* __restrict__ b,
                                  const float* __restrict__ hidden,
                                  float* __restrict__ out) {
    __shared__ float sh1[8], sh2[8];
    size_t row = blockIdx.x;
    int t = threadIdx.x;
    float4 v = ((const float4*)(x + row * D_))[t];
    float mean, rstd;
    row_moments(v, mean, rstd, sh1, sh2);
    float4 gv = ((const float4*)g)[t];
    float4 bv = ((const float4*)b)[t];
    float4 hv = ((const float4*)(hidden + row * D_))[t];
    float n0 = (v.x - mean) * rstd * gv.x + bv.x;
    float n1 = (v.y - mean) * rstd * gv.y + bv.y;
    float n2 = (v.z - mean) * rstd * gv.z + bv.z;
    float n3 = (v.w - mean) * rstd * gv.w + bv.w;
    float4 o;
    o.x = hv.x + (n0 > 0.f ? n0 : expm1f(n0));
    o.y = hv.y + (n1 > 0.f ? n1 : expm1f(n1));
    o.z = hv.z + (n2 > 0.f ? n2 : expm1f(n2));
    o.w = hv.w + (n3 > 0.f ? n3 : expm1f(n3));
    ((float4*)(out + row * D_))[t] = o;
}

// ---------------------------------------------------------------------------
// FP16 tensor-core GEMM: CTA 128x128, 8 warps (2x4), warp 64x32, BK=32,
// 4-stage cp.async (wait_group 2), 2 CTAs/SM, ldmatrix A + B.
// ---------------------------------------------------------------------------
__device__ __forceinline__ void mma_f16(float* c, const unsigned* a, const unsigned* b) {
    asm volatile(
        "mma.sync.aligned.m16n8k16.row.col.f32.f16.f16.f32 "
        "{%0,%1,%2,%3}, {%4,%5,%6,%7}, {%8,%9}, {%0,%1,%2,%3};"
        : "+f"(c[0]), "+f"(c[1]), "+f"(c[2]), "+f"(c[3])
        : "r"(a[0]), "r"(a[1]), "r"(a[2]), "r"(a[3]), "r"(b[0]), "r"(b[1]));
}

#define CP16(dst, src) \
    asm volatile("cp.async.cg.shared.global [%0], [%1], 16;\n" :: "r"(dst), "l"(src))

#define APW   20
#define ASTG  (128 * APW)
#define PBHN  136
#define BSTGW (32 * PBHN / 2)
#define NSTAGE 4
#define GEMM_SMEM_BYTES (NSTAGE * (ASTG + BSTGW) * 4)   // 75776

template <bool RELU, bool OUTHALF>
__device__ __forceinline__ void gemm_body_h(
    unsigned* sm, const __half* __restrict__ A, const __half* __restrict__ Bm,
    const float* bias, const float* res, float* C32, __half* C16,
    int N, int K, int bm, int bn) {
    unsigned* As = sm;
    unsigned* Bs = sm + NSTAGE * ASTG;
    int tid = threadIdx.x;
    int warp = tid >> 5, lane = tid & 31;
    int g = lane >> 2, tg = lane & 3;
    int wm = (warp & 1) * 64, wn = (warp >> 1) * 32;

    int arow = tid >> 1;
    const __half* aptr = A + (size_t)(bm + arow) * K + (tid & 1) * 16;
    unsigned a_dst = (unsigned)__cvta_generic_to_shared(As + arow * APW + (tid & 1) * 8);
    int brow = tid >> 3, bc = (tid & 7) * 16;
    const __half* bptr = Bm + (size_t)brow * N + bn + bc;
    unsigned b_dst = (unsigned)__cvta_generic_to_shared((__half*)Bs + brow * PBHN + bc);

    int quad = lane >> 3, j = lane & 7;
    int lrow = (quad & 1) * 8 + j;
    int lcol = wn + (quad >> 1) * 8;
    unsigned b_frag_base = (unsigned)__cvta_generic_to_shared((__half*)Bs + lrow * PBHN + lcol);
    unsigned a_frag_base = (unsigned)__cvta_generic_to_shared(
        (__half*)As + lrow * (APW * 2) + (quad >> 1) * 8);

    int ntiles = K >> 5;

    #pragma unroll
    for (int s = 0; s < NSTAGE - 1; s++) {
        if (s < ntiles) {
            const __half* ap = aptr + s * 32;
            const __half* bp = bptr + (size_t)s * 32 * N;
            unsigned ad = a_dst + s * ASTG * 4;
            unsigned bd = b_dst + s * BSTGW * 4;
            CP16(ad, ap); CP16(ad + 16, ap + 8);
            CP16(bd, bp); CP16(bd + 16, bp + 8);
        }
        asm volatile("cp.async.commit_group;\n");
    }

    float acc[4][4][4];
    #pragma unroll
    for (int mt = 0; mt < 4; mt++)
        #pragma unroll
        for (int nt = 0; nt < 4; nt++)
            #pragma unroll
            for (int r = 0; r < 4; r++) acc[mt][nt][r] = 0.f;

    for (int kt = 0; kt < ntiles; kt++) {
        asm volatile("cp.async.wait_group %0;\n" :: "n"(NSTAGE - 2));
        __syncthreads();

        int nx = kt + NSTAGE - 1;
        if (nx < ntiles) {
            int st = nx % NSTAGE;
            const __half* ap = aptr + nx * 32;
            const __half* bp = bptr + (size_t)nx * 32 * N;
            unsigned ad = a_dst + st * ASTG * 4;
            unsigned bd = b_dst + st * BSTGW * 4;
            CP16(ad, ap); CP16(ad + 16, ap + 8);
            CP16(bd, bp); CP16(bd + 16, bp + 8);
        }
        asm volatile("cp.async.commit_group;\n");

        int cur = kt % NSTAGE;
        unsigned asm_base = a_frag_base + cur * ASTG * 4 + wm * APW * 4;
        unsigned bsm = b_frag_base + cur * BSTGW * 4;
        #pragma unroll
        for (int ks = 0; ks < 2; ks++) {
            unsigned af[4][4];
            #pragma unroll
            for (int mt = 0; mt < 4; mt++) {
                unsigned aaddr = asm_base + mt * 16 * APW * 4 + ks * 32;
                asm volatile(
                    "ldmatrix.sync.aligned.m8n8.x4.shared.b16 {%0,%1,%2,%3}, [%4];"
                    : "=r"(af[mt][0]), "=r"(af[mt][1]), "=r"(af[mt][2]), "=r"(af[mt][3])
                    : "r"(aaddr));
            }
            unsigned bf[4][2];
            #pragma unroll
            for (int nb = 0; nb < 2; nb++) {
                unsigned addr = bsm + ks * 16 * (PBHN * 2) + nb * 32;
                asm volatile(
                    "ldmatrix.sync.aligned.m8n8.x4.trans.shared.b16 {%0,%1,%2,%3}, [%4];"
                    : "=r"(bf[2 * nb][0]), "=r"(bf[2 * nb][1]),
                      "=r"(bf[2 * nb + 1][0]), "=r"(bf[2 * nb + 1][1])
                    : "r"(addr));
            }
            #pragma unroll
            for (int mt = 0; mt < 4; mt++)
                #pragma unroll
                for (int nt = 0; nt < 4; nt++)
                    mma_f16(acc[mt][nt], af[mt], bf[nt]);
        }
    }

    #pragma unroll
    for (int mt = 0; mt < 4; mt++) {
        #pragma unroll
        for (int nt = 0; nt < 4; nt++) {
            int col = bn + wn + nt * 8 + tg * 2;
            #pragma unroll
            for (int h = 0; h < 2; h++) {
                int row = bm + wm + mt * 16 + g + h * 8;
                float vx = acc[mt][nt][2 * h];
                float vy = acc[mt][nt][2 * h + 1];
                if (bias) {
                    float2 bb = *(const float2*)(bias + col);
                    vx += bb.x; vy += bb.y;
                }
                if (res) {
                    float2 rr = *(const float2*)(res + (size_t)row * N + col);
                    vx += rr.x; vy += rr.y;
                }
                if (RELU) { vx = fmaxf(vx, 0.f); vy = fmaxf(vy, 0.f); }
                if (OUTHALF)
                    *(__half2*)(C16 + (size_t)row * N + col) = __floats2half2_rn(vx, vy);
                else
                    *(float2*)(C32 + (size_t)row * N + col) = make_float2(vx, vy);
            }
        }
    }
}

template <bool RELU, bool OUTHALF>
__global__ __launch_bounds__(256, 2) void mma_gemm_h(
    const __half* __restrict__ A, const __half* __restrict__ Bm,
    const float* bias, const float* res, float* C32, __half* C16,
    int M, int N, int K) {
    extern __shared__ unsigned sm[];
    gemm_body_h<RELU, OUTHALF>(sm, A, Bm, bias, res, C32, C16, N, K,
                               blockIdx.y * 128, blockIdx.x * 128);
}

struct QKVArgs {
    const __half* Bm[3];
    const float* bias[3];
    __half* C[3];
};

__global__ __launch_bounds__(256, 2) void mma_gemm_qkv(
    const __half* __restrict__ A, QKVArgs args, int M, int N, int K) {
    extern __shared__ unsigned sm[];
    int z = blockIdx.z;
    gemm_body_h<false, true>(sm, A, args.Bm[z], args.bias[z], nullptr, nullptr,
                             args.C[z], N, K, blockIdx.y * 128, blockIdx.x * 128);
}

// ---------------------------------------------------------------------------
// Small-N GEMM: C[M,64] = A[M,K] @ B[K,64]; fp32 or fp16 out
// ---------------------------------------------------------------------------
#define TAPW   20
#define TASTG  (128 * TAPW)
#define TNST   3
#define PB64   72
#define BSTG64 (32 * PB64 / 2)

template <bool OUTH>
__global__ __launch_bounds__(256, 2) void gemm_T64(
    const __half* __restrict__ A, const __half* __restrict__ Bm,
    float* C32, __half* C16, int K) {
    __shared__ unsigned smT[TNST * (TASTG + BSTG64)];
    unsigned* As = smT;
    unsigned* Bs = smT + TNST * TASTG;
    const int N = R_;
    int tid = threadIdx.x;
    int warp = tid >> 5, lane = tid & 31;
    int g = lane >> 2, tg = lane & 3;
    int wm = (warp & 3) * 32, wn = (warp >> 2) * 32;
    int bm = blockIdx.y * 128;

    int arow = tid >> 1;
    const __half* aptr = A + (size_t)(bm + arow) * K + (tid & 1) * 16;
    unsigned a_dst = (unsigned)__cvta_generic_to_shared(As + arow * TAPW + (tid & 1) * 8);
    int brow = tid >> 3, bc = (tid & 7) * 8;
    const __half* bptr = Bm + (size_t)brow * N + bc;
    unsigned b_dst = (unsigned)__cvta_generic_to_shared((__half*)Bs + brow * PB64 + bc);

    int quad = lane >> 3, j = lane & 7;
    int lrow = (quad & 1) * 8 + j;
    int lcol = wn + (quad >> 1) * 8;
    unsigned b_frag_base = (unsigned)__cvta_generic_to_shared((__half*)Bs + lrow * PB64 + lcol);

    int ntiles = K >> 5;
    #pragma unroll
    for (int s = 0; s < TNST - 1; s++) {
        unsigned ad = a_dst + s * TASTG * 4;
        unsigned bd = b_dst + s * BSTG64 * 4;
        CP16(ad, aptr + s * 32); CP16(ad + 16, aptr + s * 32 + 8);
        CP16(bd, bptr + (size_t)s * 32 * N);
        asm volatile("cp.async.commit_group;\n");
    }

    float acc[2][4][4];
    #pragma unroll
    for (int mt = 0; mt < 2; mt++)
        #pragma unroll
        for (int nt = 0; nt < 4; nt++)
            #pragma unroll
            for (int r = 0; r < 4; r++) acc[mt][nt][r] = 0.f;

    for (int kt = 0; kt < ntiles; kt++) {
        asm volatile("cp.async.wait_group %0;\n" :: "n"(TNST - 2));
        __syncthreads();
        int nx = kt + TNST - 1;
        if (nx < ntiles) {
            int st = nx % TNST;
            unsigned ad = a_dst + st * TASTG * 4;
            unsigned bd = b_dst + st * BSTG64 * 4;
            CP16(ad, aptr + nx * 32); CP16(ad + 16, aptr + nx * 32 + 8);
            CP16(bd, bptr + (size_t)nx * 32 * N);
        }
        asm volatile("cp.async.commit_group;\n");

        int cur = kt % TNST;
        const unsigned* Ab = As + cur * TASTG;
        unsigned bsm = b_frag_base + cur * BSTG64 * 4;
        #pragma unroll
        for (int ks = 0; ks < 2; ks++) {
            unsigned af[2][4];
            #pragma unroll
            for (int mt = 0; mt < 2; mt++) {
                const unsigned* p = Ab + (wm + mt * 16 + g) * TAPW + ks * 8 + tg;
                af[mt][0] = p[0];
                af[mt][1] = p[8 * TAPW];
                af[mt][2] = p[4];
                af[mt][3] = p[8 * TAPW + 4];
            }
            unsigned bf[4][2];
            #pragma unroll
            for (int nb = 0; nb < 2; nb++) {
                unsigned addr = bsm + ks * 16 * (PB64 * 2) + nb * 32;
                asm volatile(
                    "ldmatrix.sync.aligned.m8n8.x4.trans.shared.b16 {%0,%1,%2,%3}, [%4];"
                    : "=r"(bf[2 * nb][0]), "=r"(bf[2 * nb][1]),
                      "=r"(bf[2 * nb + 1][0]), "=r"(bf[2 * nb + 1][1])
                    : "r"(addr));
            }
            #pragma unroll
            for (int mt = 0; mt < 2; mt++)
                #pragma unroll
                for (int nt = 0; nt < 4; nt++)
                    mma_f16(acc[mt][nt], af[mt], bf[nt]);
        }
    }

    #pragma unroll
    for (int mt = 0; mt < 2; mt++)
        #pragma unroll
        for (int nt = 0; nt < 4; nt++) {
            int col = wn + nt * 8 + tg * 2;
            #pragma unroll
            for (int h = 0; h < 2; h++) {
                int row = bm + wm + mt * 16 + g + h * 8;
                if (OUTH)
                    *(__half2*)(C16 + (size_t)row * N + col) =
                        __floats2half2_rn(acc[mt][nt][2 * h], acc[mt][nt][2 * h + 1]);
                else
                    *(float2*)(C32 + (size_t)row * N + col) =
                        make_float2(acc[mt][nt][2 * h], acc[mt][nt][2 * h + 1]);
            }
        }
}

// ---------------------------------------------------------------------------
// Edge scores: k[src].q[dst] + T[dst,rel] + bqr[rel]
// ---------------------------------------------------------------------------
__global__ void score_kernel(const __half* __restrict__ Q, const __half* __restrict__ Km,
                             const float* __restrict__ T,
                             const int* __restrict__ src, const int* __restrict__ dst,
                             const int* __restrict__ rel, float* __restrict__ score) {
    int idx = blockIdx.x * 4 + threadIdx.y;
    int b = idx >> 15;
    int lane = threadIdx.x;
    int s = src[idx], d = dst[idx], r = rel[idx];
    const __half* kr = Km + ((size_t)b * L_ + s) * D_;
    const __half* qr = Q + ((size_t)b * L_ + d) * D_;
    float acc = 0.f;
    #pragma unroll
    for (int i = 0; i < 4; i++) {
        int c = (lane + 32 * i) * 8;
        uint4 kv = *(const uint4*)(kr + c);
        uint4 qv = *(const uint4*)(qr + c);
        const __half2* kh = (const __half2*)&kv;
        const __half2* qh = (const __half2*)&qv;
        #pragma unroll
        for (int j = 0; j < 4; j++) {
            __half2 p = __hmul2(kh[j], qh[j]);
            float2 pf = __half22float2(p);
            acc += pf.x + pf.y;
        }
    }
    #pragma unroll
    for (int o = 16; o; o >>= 1) acc += __shfl_xor_sync(0xffffffffu, acc, o);
    if (lane == 0) {
        float sc = (acc + T[((size_t)b * L_ + d) * R_ + r] + g_bqr[r]) * 0.03125f;
        sc = fminf(fmaxf(sc, -10.f), 10.f);
        score[idx] = expf(sc);
    }
}

// ---------------------------------------------------------------------------
// Deterministic binning
// ---------------------------------------------------------------------------
__global__ void zero_cnt_kernel() {
    int i = blockIdx.x * 256 + threadIdx.x;
    if (i < B_ * L_) g_cnt[i] = 0;
}

__global__ void hist_kernel(const int* __restrict__ edge_dst) {
    int idx = blockIdx.x * 256 + threadIdx.x;
    if (idx < B_ * E_) atomicAdd(&g_cnt[(idx >> 15) * L_ + edge_dst[idx]], 1);
}

__global__ void scan_kernel() {
    int b = blockIdx.x, t = threadIdx.x;
    __shared__ int s[L_];
    int c = g_cnt[b * L_ + t];
    s[t] = c;
    __syncthreads();
    for (int off = 1; off < L_; off <<= 1) {
        int v = (t >= off) ? s[t - off] : 0;
        __syncthreads();
        s[t] += v;
        __syncthreads();
    }
    g_off[b * (L_ + 1) + t] = s[t] - c;
    if (t == L_ - 1) g_off[b * (L_ + 1) + L_] = s[t];
}

__global__ void fill_block_kernel(const int* __restrict__ edge_dst) {
    __shared__ int sd[1024];
    int b = blockIdx.x >> 7;
    int nodebase = (blockIdx.x & 127) * 8;
    int warp = threadIdx.x >> 5, lane = threadIdx.x & 31;
    int node = nodebase + warp;
    int w = g_off[b * (L_ + 1) + node];
    int* pb = g_perm + b * E_;
    const int* dv = edge_dst + b * E_;
    for (int base = 0; base < E_; base += 1024) {
        __syncthreads();
        #pragma unroll
        for (int i = 0; i < 4; i++) sd[threadIdx.x + 256 * i] = dv[base + threadIdx.x + 256 * i];
        __syncthreads();
        for (int c = 0; c < 1024; c += 32) {
            int d = sd[c + lane];
            unsigned m = __ballot_sync(0xffffffffu, d == node);
            if (d == node) pb[w + __popc(m & ((1u << lane) - 1))] = base + c + lane;
            w += __popc(m);
        }
    }
}

// ---------------------------------------------------------------------------
// Fused aggregation with SMEM-staged bin metadata (R15 exact):
// term1 = (sum s*v[src])/z (fp32), Wn[r] = (sum_{rel=r} s)/z
// ---------------------------------------------------------------------------
__global__ void agg_fused_kernel(const __half* __restrict__ V,
                                 const int* __restrict__ src,
                                 const int* __restrict__ rel,
                                 const float* __restrict__ score) {
    __shared__ float ss[256];
    __shared__ int   ssn[256];
    __shared__ int   srl[256];
    int node = blockIdx.x, b = blockIdx.y;
    int t = threadIdx.x;
    int beg = g_off[b * (L_ + 1) + node];
    int end = g_off[b * (L_ + 1) + node + 1];
    int deg = end - beg;
    const int* pb = g_perm + b * E_;
    float4 acc = make_float4(0.f, 0.f, 0.f, 0.f);
    float z = 0.f;
    float W = 0.f;

    for (int base = 0; base < deg; base += 256) {
        int n = deg - base;
        if (n > 256) n = 256;
        if (t < n) {
            int e = pb[beg + base + t];
            ss[t]  = score[b * E_ + e];
            ssn[t] = src[b * E_ + e];
            srl[t] = rel[b * E_ + e];
        }
        __syncthreads();
        for (int i = 0; i < n; i++) {
            float s = ss[i];
            int sn = ssn[i];
            uint2 vw = *(const uint2*)(V + ((size_t)b * L_ + sn) * D_ + 4 * t);
            const __half2* vh = (const __half2*)&vw;
            float2 v0 = __half22float2(vh[0]), v1 = __half22float2(vh[1]);
            acc.x = fmaf(s, v0.x, acc.x);
            acc.y = fmaf(s, v0.y, acc.y);
            acc.z = fmaf(s, v1.x, acc.z);
            acc.w = fmaf(s, v1.y, acc.w);
            z += s;
        }
        if (t < R_) {
            for (int i = 0; i < n; i++)
                if (srl[i] == t) W += ss[i];
        }
        __syncthreads();
    }

    float inv = 1.0f / z;
    *(float4*)(g_term1 + ((size_t)b * L_ + node) * D_ + 4 * t) =
        make_float4(acc.x * inv, acc.y * inv, acc.z * inv, acc.w * inv);
    if (t < R_)
        g_wn_h[((size_t)b * L_ + node) * R_ + t] = __float2half(W * inv);
}

// ---------------------------------------------------------------------------
// Launch — R15 structure + T-offload (WqR precompute, T ∥ QKV on stream C).
// ---------------------------------------------------------------------------
extern "C" void kernel_launch(void* const* d_in, const int* in_sizes, int n_in,
                              void* d_out, int out_size) {
    const float* hidden  = (const float*)d_in[0];
    const float* rel_tab = (const float*)d_in[1];
    const float* Wq = (const float*)d_in[2];
    const float* bq = (const float*)d_in[3];
    const float* Wk = (const float*)d_in[4];
    const float* Wv = (const float*)d_in[5];
    const float* Wo = (const float*)d_in[6];
    const float* bo = (const float*)d_in[7];
    const float* ln0g = (const float*)d_in[8];
    const float* ln0b = (const float*)d_in[9];
    const float* ln1g = (const float*)d_in[10];
    const float* ln1b = (const float*)d_in[11];
    const float* W1 = (const float*)d_in[12];
    const float* b1 = (const float*)d_in[13];
    const float* W2 = (const float*)d_in[14];
    const float* b2 = (const float*)d_in[15];
    const float* ln2g = (const float*)d_in[16];
    const float* ln2b = (const float*)d_in[17];
    const int* esrc = (const int*)d_in[18];
    const int* edst = (const int*)d_in[19];
    const int* erel = (const int*)d_in[20];
    float* out = (float*)d_out;

    float *p_hsnorm, *p_t1, *p_out, *p_f, *p_score, *p_T, *p_term1;
    __half *p_hsnorm_h, *p_q_h, *p_k_h, *p_v_h, *p_o_h, *p_out_h, *p_h1_h, *p_wn_h;
    __half *p_wq_h, *p_wk_h, *p_wv_h, *p_wo_h, *p_w1_h, *p_w2_h, *p_rel_h, *p_rel_t_h, *p_WqR_h;
    cudaGetSymbolAddress((void**)&p_hsnorm, g_hsnorm);
    cudaGetSymbolAddress((void**)&p_hsnorm_h, g_hsnorm_h);
    cudaGetSymbolAddress((void**)&p_q_h, g_q_h);
    cudaGetSymbolAddress((void**)&p_k_h, g_k_h);
    cudaGetSymbolAddress((void**)&p_v_h, g_v_h);
    cudaGetSymbolAddress((void**)&p_o_h, g_o_h);
    cudaGetSymbolAddress((void**)&p_t1, g_t1);
    cudaGetSymbolAddress((void**)&p_out, g_out);
    cudaGetSymbolAddress((void**)&p_out_h, g_out_h);
    cudaGetSymbolAddress((void**)&p_h1_h, g_h1_h);
    cudaGetSymbolAddress((void**)&p_f, g_f);
    cudaGetSymbolAddress((void**)&p_score, g_score);
    cudaGetSymbolAddress((void**)&p_T, g_T);
    cudaGetSymbolAddress((void**)&p_term1, g_term1);
    cudaGetSymbolAddress((void**)&p_wn_h, g_wn_h);
    cudaGetSymbolAddress((void**)&p_wq_h, g_wq_h);
    cudaGetSymbolAddress((void**)&p_wk_h, g_wk_h);
    cudaGetSymbolAddress((void**)&p_wv_h, g_wv_h);
    cudaGetSymbolAddress((void**)&p_wo_h, g_wo_h);
    cudaGetSymbolAddress((void**)&p_w1_h, g_w1_h);
    cudaGetSymbolAddress((void**)&p_w2_h, g_w2_h);
    cudaGetSymbolAddress((void**)&p_rel_h, g_rel_h);
    cudaGetSymbolAddress((void**)&p_rel_t_h, g_rel_t_h);
    cudaGetSymbolAddress((void**)&p_WqR_h, g_WqR_h);

    cudaFuncSetAttribute((const void*)mma_gemm_h<false, false>,
                         cudaFuncAttributeMaxDynamicSharedMemorySize, GEMM_SMEM_BYTES);
    cudaFuncSetAttribute((const void*)mma_gemm_h<false, true>,
                         cudaFuncAttributeMaxDynamicSharedMemorySize, GEMM_SMEM_BYTES);
    cudaFuncSetAttribute((const void*)mma_gemm_h<true, true>,
                         cudaFuncAttributeMaxDynamicSharedMemorySize, GEMM_SMEM_BYTES);
    cudaFuncSetAttribute((const void*)mma_gemm_qkv,
                         cudaFuncAttributeMaxDynamicSharedMemorySize, GEMM_SMEM_BYTES);

    cudaStream_t sA, sB, sC;
    cudaStreamCreateWithFlags(&sA, cudaStreamNonBlocking);
    cudaStreamCreateWithFlags(&sB, cudaStreamNonBlocking);
    cudaStreamCreateWithFlags(&sC, cudaStreamNonBlocking);
    cudaEvent_t evFork, evA, evA2, evB, evLn0, evT;
    cudaEventCreateWithFlags(&evFork, cudaEventDisableTiming);
    cudaEventCreateWithFlags(&evA, cudaEventDisableTiming);
    cudaEventCreateWithFlags(&evA2, cudaEventDisableTiming);
    cudaEventCreateWithFlags(&evB, cudaEventDisableTiming);
    cudaEventCreateWithFlags(&evLn0, cudaEventDisableTiming);
    cudaEventCreateWithFlags(&evT, cudaEventDisableTiming);

    cudaEventRecord(evFork, 0);
    cudaStreamWaitEvent(sA, evFork, 0);
    cudaStreamWaitEvent(sB, evFork, 0);
    cudaStreamWaitEvent(sC, evFork, 0);

    // Branch A: conversions + rel transpose, then WqR/bqr precompute
    {
        CvtArgs a;
        const float* srcs[NSEG] = {Wq, Wk, Wv, Wo, W1, W2, rel_tab};
        __half* dsts[NSEG] = {p_wq_h, p_wk_h, p_wv_h, p_wo_h, p_w1_h, p_w2_h, p_rel_h};
        int ns[NSEG] = {D_ * D_, D_ * D_, D_ * D_, D_ * D_, D_ * DF_, DF_ * D_, R_ * D_};
        int cum = 0;
        for (int i = 0; i < NSEG; i++) {
            a.src[i] = srcs[i]; a.dst[i] = dsts[i]; a.n[i] = ns[i];
            a.cum[i] = cum;
            cum += (ns[i] + 2047) / 2048;
        }
        cvt_f2h_multi<<<cum, 256, 0, sA>>>(a);
    }
    rel_transpose<<<(D_ * R_) / 256, 256, 0, sA>>>(rel_tab);
    cudaEventRecord(evA, sA);    // weights fp16 ready for QKV
    gemm_T64<true><<<dim3(1, D_ / 128), 256, 0, sA>>>(p_wq_h, p_rel_t_h, nullptr, p_WqR_h, D_);
    bqr_kernel<<<R_, 32, 0, sA>>>(bq, rel_tab);
    cudaEventRecord(evA2, sA);

    // Branch B: edge binning
    zero_cnt_kernel<<<(B_ * L_) / 256, 256, 0, sB>>>();
    hist_kernel<<<(B_ * E_) / 256, 256, 0, sB>>>(edst);
    scan_kernel<<<B_, L_, 0, sB>>>();
    fill_block_kernel<<<512, 256, 0, sB>>>(edst);
    cudaEventRecord(evB, sB);

    // Main: ln0
    ln_dual_kernel<<<M_, 256>>>(hidden, ln0g, ln0b, p_hsnorm, p_hsnorm_h);
    cudaEventRecord(evLn0, 0);

    cudaStreamWaitEvent(0, evA, 0);

    // QKV (main) ; T = hsnorm @ WqR (stream C, concurrent with QKV)
    QKVArgs qkv;
    qkv.Bm[0] = p_wq_h; qkv.Bm[1] = p_wk_h; qkv.Bm[2] = p_wv_h;
    qkv.bias[0] = bq; qkv.bias[1] = nullptr; qkv.bias[2] = nullptr;
    qkv.C[0] = p_q_h; qkv.C[1] = p_k_h; qkv.C[2] = p_v_h;
    dim3 gQKV(D_ / 128, M_ / 128, 3);
    mma_gemm_qkv<<<gQKV, 256, GEMM_SMEM_BYTES>>>(p_hsnorm_h, qkv, M_, D_, D_);

    cudaStreamWaitEvent(sC, evLn0, 0);
    cudaStreamWaitEvent(sC, evA2, 0);
    gemm_T64<false><<<dim3(1, M_ / 128), 256, 0, sC>>>(p_hsnorm_h, p_WqR_h, p_T, nullptr, D_);
    cudaEventRecord(evT, sC);

    // score after QKV (main) + T (C)
    cudaStreamWaitEvent(0, evT, 0);
    score_kernel<<<(B_ * E_) / 4, dim3(32, 4)>>>(p_q_h, p_k_h, p_T, esrc, edst, erel, p_score);

    cudaStreamWaitEvent(0, evB, 0);

    // fused agg (term1 + Wn, smem-staged)
    agg_fused_kernel<<<dim3(L_, B_), 256>>>(p_v_h, esrc, erel, p_score);

    // o = Wn @ rel + term1 (fp16 out, K=64)
    dim3 gD(D_ / 128, M_ / 128);
    mma_gemm_h<false, true><<<gD, 256, GEMM_SMEM_BYTES>>>(
        p_wn_h, p_rel_h, nullptr, p_term1, nullptr, p_o_h, M_, D_, R_);

    // t1 = hs_norm + o @ Wo + bo ; ln1 -> out (dual)
    mma_gemm_h<false, false><<<gD, 256, GEMM_SMEM_BYTES>>>(
        p_o_h, p_wo_h, bo, p_hsnorm, p_t1, nullptr, M_, D_, D_);
    ln_dual_kernel<<<M_, 256>>>(p_t1, ln1g, ln1b, p_out, p_out_h);

    // FFN
    dim3 gDF(DF_ / 128, M_ / 128);
    mma_gemm_h<true, true><<<gDF, 256, GEMM_SMEM_BYTES>>>(
        p_out_h, p_w1_h, b1, nullptr, nullptr, p_h1_h, M_, DF_, D_);
    mma_gemm_h<false, false><<<gD, 256, GEMM_SMEM_BYTES>>>(
        p_h1_h, p_w2_h, b2, p_out, p_f, nullptr, M_, D_, DF_);

    // final
    ln_elu_res_kernel<<<M_, 256>>>(p_f, ln2g, ln2b, hidden, out);

    cudaEventDestroy(evFork); cudaEventDestroy(evA); cudaEventDestroy(evA2);
    cudaEventDestroy(evB); cudaEventDestroy(evLn0); cudaEventDestroy(evT);
    cudaStreamDestroy(sA); cudaStreamDestroy(sB); cudaStreamDestroy(sC);
}